// round 5
// baseline (speedup 1.0000x reference)
#include <cuda_runtime.h>
#include <cstdint>

// ================= problem constants =================
#define NB   1024
#define IIC  128
#define TILES_PER_N 7
#define NTILES (NB*TILES_PER_N)     // 7168
#define GRID_MAIN 304               // 152 CTAs per i-half

// ================= scratch =================
// g_R[(n*28+h')][idx 0..31][l 0..31]  (tf32-rounded floats)
__device__ float g_R[(size_t)NB*28*32*32];   // 117 MB

// ================= smem layout (per CTA) =================
#define WS_BYTES   (36*4*32*16)       // 73728  (S=36, mt=4, lane=32, uint4)
#define ACT_FLOATS 4096               // per buffer: 16384 B
#define SM_TOTAL   (WS_BYTES + 2*ACT_FLOATS*4)   // 106496

__device__ __forceinline__ uint32_t f2tf32(float v) {
    uint32_t o; asm("cvt.rna.tf32.f32 %0, %1;" : "=r"(o) : "f"(v)); return o;
}

__device__ __forceinline__ void mma_tf32(float4& d, const uint4& a, const uint2& b) {
    asm volatile(
        "mma.sync.aligned.m16n8k8.row.col.f32.tf32.tf32.f32 "
        "{%0,%1,%2,%3}, {%4,%5,%6,%7}, {%8,%9}, {%0,%1,%2,%3};"
        : "+f"(d.x), "+f"(d.y), "+f"(d.z), "+f"(d.w)
        : "r"(a.x), "r"(a.y), "r"(a.z), "r"(a.w), "r"(b.x), "r"(b.y));
}

// ================= prep kernel: build g_R (unchanged, validated R4) =================
__global__ __launch_bounds__(128) void prep_kernel(const float* __restrict__ x) {
    __shared__ float xs[64 * 29];
    const int p = blockIdx.x;            // n*28 + h'
    const int n = p / 28, h = p - n * 28;
    const int tid = threadIdx.x;

    for (int e = tid; e < 64 * 28; e += 128) {
        const int c = e / 28, u = e - c * 28;
        xs[c * 29 + u] = x[(((size_t)n * 64 + c) * 28 + h) * 28 + u];
    }
    __syncthreads();

    float* Rout = g_R + (size_t)p * (32 * 32);
    const int l = tid & 31;
    const int q0 = tid >> 5;
    #pragma unroll
    for (int qq = 0; qq < 8; ++qq) {
        const int q = qq * 4 + q0;
        float v;
        if (q < 28) {
            int u1 = q - 1; if (u1 < 0) u1 += 28;
            int u2 = q - 2; if (u2 < 0) u2 += 28;
            v = xs[l * 29 + u1] + xs[(32 + l) * 29 + u2];
        } else if (q == 28) v = xs[(32 + l) * 29 + 25];   // k=0, w=0
        else if (q == 29)   v = xs[l * 29 + 27];          // k=0, w=1
        else if (q == 30)   v = xs[l * 29 + 0];           // k=2, w=0
        else                v = xs[(32 + l) * 29 + 26];   // k=2, w=27
        Rout[q * 32 + l] = __uint_as_float(f2tf32(v));
    }
}

// ================= staging helpers =================
struct StageData { float4 a0, b0, a1, b1; };

__device__ __forceinline__ int chunk_off(int c, int h, int rowb,
                                         int i0, int i1, int i2, bool mv) {
    const int j = (c * 11) >> 5;      // c/3 for c in [0,8]
    const int k = c - j * 3;
    const int hp = h + j - 1;
    if (!mv || (unsigned)hp >= 28u) return -1;
    const int idx = (k == 0) ? i0 : (k == 1) ? i1 : i2;
    return ((rowb + hp) * 32 + idx) << 5;
}

__device__ __forceinline__ StageData stage_ld(int off, int sl0) {
    StageData s;
    if (off >= 0) {
        const float4* p = reinterpret_cast<const float4*>(g_R + off);
        s.a0 = p[sl0 * 2 + 0]; s.b0 = p[sl0 * 2 + 1];   // sL = sl0
        s.a1 = p[sl0 * 2 + 4]; s.b1 = p[sl0 * 2 + 5];   // sL = sl0+2
    } else {
        s.a0 = s.b0 = s.a1 = s.b1 = make_float4(0.f, 0.f, 0.f, 0.f);
    }
    return s;
}

__device__ __forceinline__ void stage_st(float* buf, int stb_a, int stb_b,
                                         const StageData& s) {
    *reinterpret_cast<float4*>(buf + stb_a)     = make_float4(s.a0.x, s.b0.x, s.a0.y, s.b0.y);
    *reinterpret_cast<float4*>(buf + stb_a + 4) = make_float4(s.a0.z, s.b0.z, s.a0.w, s.b0.w);
    *reinterpret_cast<float4*>(buf + stb_b)     = make_float4(s.a1.x, s.b1.x, s.a1.y, s.b1.y);
    *reinterpret_cast<float4*>(buf + stb_b + 4) = make_float4(s.a1.z, s.b1.z, s.a1.w, s.b1.w);
}

// ================= main kernel =================
__global__ __launch_bounds__(256, 2) void main_kernel(const float* __restrict__ Wg,
                                                      float* __restrict__ out) {
    extern __shared__ char smem[];
    float* ws = reinterpret_cast<float*>(smem);
    const uint4* ws4 = reinterpret_cast<const uint4*>(smem);
    float* act0 = reinterpret_cast<float*>(smem + WS_BYTES);
    float* act1 = act0 + ACT_FLOATS;

    const int tid  = threadIdx.x;
    const int lane = tid & 31;
    const int wid  = tid >> 5;
    const int warp_i = wid & 1;       // i-quarter within the 64i half (2 mt each)
    const int warp_m = wid >> 1;      // m-quarter (32 m each)
    const int ihalf  = blockIdx.x & 1;

    // ---- weights (64 i-half) -> fragment-ready smem, once per CTA ----
    for (int e = tid; e < 64 * 288; e += 256) {
        const int kko = e >> 6;                 // l*9 + c
        const int il  = e & 63;
        const float v = Wg[kko * 128 + ihalf * 64 + il];
        const int l = kko / 9;
        const int c = kko - l * 9;
        const int kp = c * 32 + l;
        const int S = kp >> 3, kk8 = kp & 7;
        const int r = il & 15, mt = il >> 4;
        const int t = ((r & 7) << 2) + (kk8 & 3);
        const int reg = (r >> 3) + ((kk8 >> 2) << 1);
        ws[(((S << 2) + mt) * 32 + t) * 4 + reg] = __uint_as_float(f2tf32(v));
    }
    // (first tile's post-stage0 __syncthreads orders these writes before any MMA)

    // ---- per-thread staging identity: one m-row, two sL values ----
    const int m_loc = tid & 127;
    const int sl0   = tid >> 7;          // handles sL = sl0 and sl0+2
    const int nt    = m_loc >> 3;
    const int stb_a = ((sl0 * 16 + nt) * 64)       + (((m_loc & 7) ^ sl0)       << 3);
    const int stb_b = (((sl0 + 2) * 16 + nt) * 64) + (((m_loc & 7) ^ (sl0 + 2)) << 3);

    for (int g = (blockIdx.x >> 1); g < NTILES; g += (gridDim.x >> 1)) {
        const int n  = g / TILES_PER_N;
        const int tt = g - n * TILES_PER_N;
        const int mg = tt * 128 + m_loc;
        const bool mv = (mg < 784);
        const int h  = mg / 28;
        const int wp = mg - h * 28;
        const int ik0 = (wp == 0) ? 28 : (wp == 1) ? 29 : (wp - 1);
        const int ik1 = wp;
        const int ik2 = (wp == 0) ? 30 : (wp == 27) ? 31 : (wp + 1);
        const int rowb = n * 28;

        // ---- stage chunk 0 ----
        {
            StageData s0 = stage_ld(chunk_off(0, h, rowb, ik0, ik1, ik2, mv), sl0);
            stage_st(act0, stb_a, stb_b, s0);
        }
        __syncthreads();

        float4 acc[2][4];
        #pragma unroll
        for (int a = 0; a < 2; ++a)
            #pragma unroll
            for (int b = 0; b < 4; ++b)
                acc[a][b] = make_float4(0.f, 0.f, 0.f, 0.f);

        // ---- 9 chunks: LDG(c+1) -> MMA(c) -> STS(c+1) -> sync ----
        #pragma unroll 1
        for (int c = 0; c < 9; ++c) {
            StageData sn;
            if (c < 8)
                sn = stage_ld(chunk_off(c + 1, h, rowb, ik0, ik1, ik2, mv), sl0);

            const float* bufc = (c & 1) ? act1 : act0;
            const uint2* b2 = reinterpret_cast<const uint2*>(bufc);
            #pragma unroll
            for (int s = 0; s < 4; ++s) {
                uint4 afr[2];
                #pragma unroll
                for (int mtl = 0; mtl < 2; ++mtl)
                    afr[mtl] = ws4[((((c * 4 + s) << 2) + warp_i * 2 + mtl)) * 32 + lane];
                uint2 bfr[4];
                const int lsw = (((lane >> 2) ^ s) << 2) + (lane & 3);
                #pragma unroll
                for (int ntl = 0; ntl < 4; ++ntl)
                    bfr[ntl] = b2[((s << 4) + warp_m * 4 + ntl) * 32 + lsw];
                #pragma unroll
                for (int mtl = 0; mtl < 2; ++mtl)
                    #pragma unroll
                    for (int ntl = 0; ntl < 4; ++ntl)
                        mma_tf32(acc[mtl][ntl], afr[mtl], bfr[ntl]);
            }

            if (c < 8)
                stage_st((c & 1) ? act0 : act1, stb_a, stb_b, sn);
            __syncthreads();
        }

        // ---- epilogue: coalesced float2 stores ----
        const size_t outn = (size_t)n * (IIC * 784);
        #pragma unroll
        for (int mtl = 0; mtl < 2; ++mtl) {
            const int i0 = ihalf * 64 + (warp_i * 2 + mtl) * 16 + (lane >> 2);
            #pragma unroll
            for (int ntl = 0; ntl < 4; ++ntl) {
                const int mloc = warp_m * 32 + ntl * 8 + ((lane & 3) << 1);
                const int mgo = tt * 128 + mloc;
                if (mgo < 784) {
                    const float4 v = acc[mtl][ntl];
                    *reinterpret_cast<float2*>(out + outn + (size_t)i0 * 784 + mgo)
                        = make_float2(v.x, v.y);
                    *reinterpret_cast<float2*>(out + outn + (size_t)(i0 + 8) * 784 + mgo)
                        = make_float2(v.z, v.w);
                }
            }
        }
        // next tile's stage0 write to act0 is safe: all c=8 MMAs completed before the
        // final chunk __syncthreads; epilogue touches only registers/global.
    }
}

// ================= launch =================
extern "C" void kernel_launch(void* const* d_in, const int* in_sizes, int n_in,
                              void* d_out, int out_size) {
    const float* x  = (const float*)d_in[0];   // (1024,64,28,28)
    const float* Wg = (const float*)d_in[1];   // (32,3,3,128)
    float* out = (float*)d_out;                // (1024,128,28,28)

    prep_kernel<<<NB * 28, 128>>>(x);

    cudaFuncSetAttribute(main_kernel, cudaFuncAttributeMaxDynamicSharedMemorySize, SM_TOTAL);
    main_kernel<<<GRID_MAIN, 256, SM_TOTAL>>>(Wg, out);
}

// round 6
// speedup vs baseline: 1.7549x; 1.7549x over previous
#include <cuda_runtime.h>
#include <cstdint>

// ================= problem constants =================
#define NB   1024
#define IIC  128
#define MGLOB (NB*784)            // 802816 flattened output rows
#define MT    256                 // m per tile
#define NTILES (MGLOB/MT)         // 3136 exact
#define GRID_MAIN 152

// ================= scratch =================
// g_R[(n*28+h')][idx 0..31][l 0..31]  (tf32-rounded floats, 128B rows)
__device__ float g_R[(size_t)NB*28*32*32];   // 117 MB

// ================= smem layout =================
#define WS_BYTES   (36*8*32*16)                 // 147456 (S=36, mt=8, lane=32, uint4)
#define ACT_FLOATS 8192                         // 4s * 32nt * 2reg * 32 = 32KB
#define ACT0_OFF   WS_BYTES                     // 147456
#define ACT1_OFF   (ACT0_OFF + ACT_FLOATS*4)    // 180224
#define OFF9_OFF   (ACT1_OFF + ACT_FLOATS*4)    // 212992
#define SM_TOTAL   (OFF9_OFF + 9*MT*4)          // 222208

__device__ __forceinline__ uint32_t f2tf32(float v) {
    uint32_t o; asm("cvt.rna.tf32.f32 %0, %1;" : "=r"(o) : "f"(v)); return o;
}

__device__ __forceinline__ void mma_tf32(float4& d, const uint4& a, const uint2& b) {
    asm volatile(
        "mma.sync.aligned.m16n8k8.row.col.f32.tf32.tf32.f32 "
        "{%0,%1,%2,%3}, {%4,%5,%6,%7}, {%8,%9}, {%0,%1,%2,%3};"
        : "+f"(d.x), "+f"(d.y), "+f"(d.z), "+f"(d.w)
        : "r"(a.x), "r"(a.y), "r"(a.z), "r"(a.w), "r"(b.x), "r"(b.y));
}

// ================= prep kernel: build g_R (validated R4/R5) =================
__global__ __launch_bounds__(128) void prep_kernel(const float* __restrict__ x) {
    __shared__ float xs[64 * 29];
    const int p = blockIdx.x;            // n*28 + h'
    const int n = p / 28, h = p - n * 28;
    const int tid = threadIdx.x;

    for (int e = tid; e < 64 * 28; e += 128) {
        const int c = e / 28, u = e - c * 28;
        xs[c * 29 + u] = x[(((size_t)n * 64 + c) * 28 + h) * 28 + u];
    }
    __syncthreads();

    float* Rout = g_R + (size_t)p * (32 * 32);
    const int l = tid & 31;
    const int q0 = tid >> 5;
    #pragma unroll
    for (int qq = 0; qq < 8; ++qq) {
        const int q = qq * 4 + q0;
        float v;
        if (q < 28) {
            int u1 = q - 1; if (u1 < 0) u1 += 28;
            int u2 = q - 2; if (u2 < 0) u2 += 28;
            v = xs[l * 29 + u1] + xs[(32 + l) * 29 + u2];
        } else if (q == 28) v = xs[(32 + l) * 29 + 25];   // k=0, w=0
        else if (q == 29)   v = xs[l * 29 + 27];          // k=0, w=1
        else if (q == 30)   v = xs[l * 29 + 0];           // k=2, w=0
        else                v = xs[(32 + l) * 29 + 26];   // k=2, w=27
        Rout[q * 32 + l] = __uint_as_float(f2tf32(v));
    }
}

// fragment-ready act addressing: value (m = nt*8+mrel, l = slot*4+pos), slot = 2s+reg
// float offset = ((s*32+nt)*2+reg)*32 + ((mrel^slot)<<2) + pos   (XOR kills STS/LDS conflicts)
__device__ __forceinline__ int frag_off(int s, int nt, int reg, int mrel, int pos) {
    const int slot = s * 2 + reg;
    return (((s * 32 + nt) * 2 + reg) << 5) + (((mrel ^ slot)) << 2) + pos;
}

// ================= main kernel =================
__global__ __launch_bounds__(512, 1) void main_kernel(const float* __restrict__ Wg,
                                                      float* __restrict__ out) {
    extern __shared__ char smem[];
    float* ws = reinterpret_cast<float*>(smem);
    const uint4* ws4 = reinterpret_cast<const uint4*>(smem);
    float* act0 = reinterpret_cast<float*>(smem + ACT0_OFF);
    float* act1 = reinterpret_cast<float*>(smem + ACT1_OFF);
    int*   off9 = reinterpret_cast<int*>(smem + OFF9_OFF);

    const int tid  = threadIdx.x;
    const int lane = tid & 31;
    const int w    = tid >> 5;
    const int warp_i = w & 1;       // 64i half
    const int warp_m = w >> 1;      // 8 m-octants of 32m

    // ---- weights (full 128i) -> fragment-ready smem, once ----
    for (int e = tid; e < 288 * 128; e += 512) {
        const int kko = e >> 7;               // l*9 + c
        const int i   = e & 127;
        const float v = Wg[e];
        const int l = kko / 9;
        const int c = kko - l * 9;
        const int kp = c * 32 + l;
        const int S = kp >> 3, kk8 = kp & 7;
        const int mt = i >> 4, r = i & 15;
        const int t = ((r & 7) << 2) + (kk8 & 3);
        const int reg = (r >> 3) + ((kk8 >> 2) << 1);
        ws[(((S << 3) + mt) * 32 + t) * 4 + reg] = __uint_as_float(f2tf32(v));
    }

    // per-thread staging identity: round q covers rows m = w*16 + q*4 + (lane>>3)
    const int srow4 = lane >> 3;      // row within group of 4
    const int slot  = lane & 7;       // 16B slot (l = slot*4 .. +3)
    const int s_s   = slot >> 1;
    const int s_reg = slot & 1;

    for (int g = blockIdx.x; g < NTILES; g += gridDim.x) {
        const int mbase = g * MT;

        // ---- off9 table for this tile ----
        for (int e = tid; e < 9 * MT; e += 512) {
            const int c = e >> 8;
            const int m = e & 255;
            const int mg = mbase + m;
            const int n  = mg / 784;
            const int r  = mg - n * 784;
            const int h  = r / 28;
            const int wp = r - h * 28;
            const int j  = (c * 11) >> 5;     // c/3
            const int k  = c - j * 3;
            const int hp = h + j - 1;
            int off = -1;
            if ((unsigned)hp < 28u) {
                int idx;
                if (k == 0)      idx = (wp == 0) ? 28 : (wp == 1) ? 29 : (wp - 1);
                else if (k == 1) idx = wp;
                else             idx = (wp == 0) ? 30 : (wp == 27) ? 31 : (wp + 1);
                off = (((n * 28 + hp) << 5) + idx) << 5;
            }
            off9[e] = off;
        }
        __syncthreads();

        // ---- stage chunk 0 into act0 ----
        #pragma unroll
        for (int q = 0; q < 4; ++q) {
            const int m_loc = (w << 4) + (q << 2) + srow4;
            const int off = off9[m_loc];      // c=0
            float4 v = make_float4(0.f, 0.f, 0.f, 0.f);
            if (off >= 0) v = *reinterpret_cast<const float4*>(g_R + off + (slot << 2));
            *reinterpret_cast<float4*>(act0 + frag_off(s_s, m_loc >> 3, s_reg, m_loc & 7, 0)) = v;
        }
        __syncthreads();

        float4 acc[4][4];
        #pragma unroll
        for (int a = 0; a < 4; ++a)
            #pragma unroll
            for (int b = 0; b < 4; ++b)
                acc[a][b] = make_float4(0.f, 0.f, 0.f, 0.f);

        // ---- 9 chunks: LDG(c+1) -> MMA(c) -> STS(c+1) -> sync ----
        #pragma unroll 1
        for (int c = 0; c < 9; ++c) {
            float4 sv[4];
            if (c < 8) {
                #pragma unroll
                for (int q = 0; q < 4; ++q) {
                    const int m_loc = (w << 4) + (q << 2) + srow4;
                    const int off = off9[(c + 1) * MT + m_loc];
                    sv[q] = make_float4(0.f, 0.f, 0.f, 0.f);
                    if (off >= 0)
                        sv[q] = *reinterpret_cast<const float4*>(g_R + off + (slot << 2));
                }
            }

            const float* bufc = (c & 1) ? act1 : act0;
            #pragma unroll
            for (int s = 0; s < 4; ++s) {
                uint4 afr[4];
                #pragma unroll
                for (int mtl = 0; mtl < 4; ++mtl)
                    afr[mtl] = ws4[(((c * 4 + s) << 3) + warp_i * 4 + mtl) * 32 + lane];
                uint2 bfr[4];
                const int mrel = lane >> 2, pos = lane & 3;
                #pragma unroll
                for (int ntl = 0; ntl < 4; ++ntl) {
                    const int nt = warp_m * 4 + ntl;
                    bfr[ntl].x = __float_as_uint(bufc[frag_off(s, nt, 0, mrel, pos)]);
                    bfr[ntl].y = __float_as_uint(bufc[frag_off(s, nt, 1, mrel, pos)]);
                }
                #pragma unroll
                for (int mtl = 0; mtl < 4; ++mtl)
                    #pragma unroll
                    for (int ntl = 0; ntl < 4; ++ntl)
                        mma_tf32(acc[mtl][ntl], afr[mtl], bfr[ntl]);
            }

            if (c < 8) {
                float* bufn = (c & 1) ? act0 : act1;
                #pragma unroll
                for (int q = 0; q < 4; ++q) {
                    const int m_loc = (w << 4) + (q << 2) + srow4;
                    *reinterpret_cast<float4*>(
                        bufn + frag_off(s_s, m_loc >> 3, s_reg, m_loc & 7, 0)) = sv[q];
                }
            }
            __syncthreads();
        }

        // ---- epilogue: coalesced float2 stores (no padding, every m valid) ----
        #pragma unroll
        for (int mtl = 0; mtl < 4; ++mtl) {
            const int i0 = warp_i * 64 + mtl * 16 + (lane >> 2);
            #pragma unroll
            for (int ntl = 0; ntl < 4; ++ntl) {
                const int mgo = mbase + warp_m * 32 + ntl * 8 + ((lane & 3) << 1);
                const int n = mgo / 784;
                const int r = mgo - n * 784;     // float2 never straddles n (mgo even)
                const float4 v = acc[mtl][ntl];
                float* ob = out + (size_t)n * (IIC * 784) + r;
                *reinterpret_cast<float2*>(ob + (size_t)i0 * 784)       = make_float2(v.x, v.y);
                *reinterpret_cast<float2*>(ob + (size_t)(i0 + 8) * 784) = make_float2(v.z, v.w);
            }
        }
        __syncthreads();   // protect off9/act rewrite next tile
    }
}

// ================= launch =================
extern "C" void kernel_launch(void* const* d_in, const int* in_sizes, int n_in,
                              void* d_out, int out_size) {
    const float* x  = (const float*)d_in[0];   // (1024,64,28,28)
    const float* Wg = (const float*)d_in[1];   // (32,3,3,128)
    float* out = (float*)d_out;                // (1024,128,28,28)

    prep_kernel<<<NB * 28, 128>>>(x);

    cudaFuncSetAttribute(main_kernel, cudaFuncAttributeMaxDynamicSharedMemorySize, SM_TOTAL);
    main_kernel<<<GRID_MAIN, 512, SM_TOTAL>>>(Wg, out);
}